// round 1
// baseline (speedup 1.0000x reference)
#include <cuda_runtime.h>

// ---------------------------------------------------------------------------
// HeteroGAT: 2-layer heterogeneous GAT + (collapsed) transformer + linear head
// ---------------------------------------------------------------------------

#define NAUT   16384
#define NPAP   16384
#define IN_DIM 128
#define HID    64
#define NHEAD  4
#define DHEAD  16
#define OUTF   349
#define NEDGE  262144
#define NEG_SLOPE 0.2f
#define ENC_NEG_INF 0x007FFFFFu   // enc(-inf)

constexpr long long NI  = (long long)NAUT * IN_DIM;
constexpr long long NHF = (long long)NAUT * HID;
constexpr long long N4  = (long long)NAUT * NHEAD;

constexpr long long OFF_HA    = 0;
constexpr long long OFF_HP    = OFF_HA + NI;
constexpr long long OFF_FA0   = OFF_HP + NI;
constexpr long long OFF_FP0   = OFF_FA0 + NHF;
constexpr long long OFF_FP1   = OFF_FP0 + NHF;
constexpr long long OFF_FP2   = OFF_FP1 + NHF;
constexpr long long OFF_FA2   = OFF_FP2 + NHF;
constexpr long long OFF_OUTP  = OFF_FA2 + NHF;
constexpr long long OFF_OUTA  = OFF_OUTP + NHF;
constexpr long long OFF_HA1   = OFF_OUTA + NHF;
constexpr long long OFF_HP1   = OFF_HA1 + NHF;
constexpr long long OFF_F1A   = OFF_HP1 + NHF;
constexpr long long OFF_F1PD  = OFF_F1A + NHF;
constexpr long long OFF_F1PC  = OFF_F1PD + NHF;
constexpr long long OFF_OUTP1 = OFF_F1PC + NHF;
constexpr long long OFF_HF    = OFF_OUTP1 + NHF;
constexpr long long OFF_EL    = OFF_HF + 2 * NHF;
constexpr long long OFF_M     = OFF_EL + 10 * N4;
constexpr long long OFF_DEN   = OFF_M + 5 * N4;
constexpr long long OFF_C     = OFF_DEN + 5 * N4;
constexpr long long SCRATCH_TOTAL = OFF_C + 1;

__device__ float g_scratch[SCRATCH_TOTAL];

__device__ __forceinline__ unsigned encf(float f) {
    unsigned u = __float_as_uint(f);
    return (u & 0x80000000u) ? ~u : (u | 0x80000000u);
}
__device__ __forceinline__ float decf(unsigned u) {
    return __uint_as_float((u & 0x80000000u) ? (u ^ 0x80000000u) : ~u);
}
__device__ __forceinline__ float leaky(float x) {
    return x > 0.f ? x : NEG_SLOPE * x;
}

__global__ void fill_kernel(unsigned* __restrict__ p, unsigned v, long long n) {
    long long i = (long long)blockIdx.x * blockDim.x + threadIdx.x;
    if (i < n) p[i] = v;
}

__global__ void scale_kernel(const float* __restrict__ xa, const float* __restrict__ xp,
                             const float* __restrict__ ntype,
                             float* __restrict__ ha, float* __restrict__ hp) {
    long long i = (long long)blockIdx.x * blockDim.x + threadIdx.x;
    if (i >= NI) return;
    int c = (int)(i & (IN_DIM - 1));
    ha[i] = xa[i] * ntype[c];
    hp[i] = xp[i] * ntype[IN_DIM + c];
}

__global__ __launch_bounds__(256) void gemm_kernel(
    const float* __restrict__ A, const float* __restrict__ W,
    const float* __restrict__ bias, float* __restrict__ C,
    int K, int Ncols) {
    __shared__ __align__(16) float As[64][65];
    __shared__ __align__(16) float Ws[64][64];
    int row0 = blockIdx.x * 64;
    int col0 = blockIdx.y * 64;
    int tid = threadIdx.x;
    int tr = (tid >> 4) * 4;
    int tc = (tid & 15) * 4;
    float acc[4][4] = {};
    for (int kt = 0; kt < K; kt += 64) {
#pragma unroll
        for (int i = 0; i < 16; i++) {
            int idx = tid + i * 256;
            int r = idx >> 6, k = idx & 63;
            As[k][r] = A[(long long)(row0 + r) * K + kt + k];
        }
#pragma unroll
        for (int i = 0; i < 16; i++) {
            int idx = tid + i * 256;
            int k = idx >> 6, c = idx & 63;
            int gc = col0 + c;
            Ws[k][c] = (gc < Ncols) ? W[(long long)(kt + k) * Ncols + gc] : 0.0f;
        }
        __syncthreads();
#pragma unroll 16
        for (int k = 0; k < 64; k++) {
            float a0 = As[k][tr], a1 = As[k][tr + 1], a2 = As[k][tr + 2], a3 = As[k][tr + 3];
            float4 w = *(const float4*)&Ws[k][tc];
            acc[0][0] += a0 * w.x; acc[0][1] += a0 * w.y; acc[0][2] += a0 * w.z; acc[0][3] += a0 * w.w;
            acc[1][0] += a1 * w.x; acc[1][1] += a1 * w.y; acc[1][2] += a1 * w.z; acc[1][3] += a1 * w.w;
            acc[2][0] += a2 * w.x; acc[2][1] += a2 * w.y; acc[2][2] += a2 * w.z; acc[2][3] += a2 * w.w;
            acc[3][0] += a3 * w.x; acc[3][1] += a3 * w.y; acc[3][2] += a3 * w.z; acc[3][3] += a3 * w.w;
        }
        __syncthreads();
    }
#pragma unroll
    for (int i = 0; i < 4; i++) {
        long long r = row0 + tr + i;
#pragma unroll
        for (int j = 0; j < 4; j++) {
            int c = col0 + tc + j;
            if (c < Ncols) {
                float v = acc[i][j];
                if (bias) v += bias[c];
                C[r * Ncols + c] = v;
            }
        }
    }
}

__global__ void eler_kernel(const float* __restrict__ F, const float* __restrict__ avec,
                            float* __restrict__ out) {
    int i = blockIdx.x * blockDim.x + threadIdx.x;
    if (i >= NAUT * NHEAD) return;
    int node = i >> 2, h = i & 3;
    const float4* f = (const float4*)(F + (long long)node * HID + h * DHEAD);
    const float4* a = (const float4*)(avec + h * DHEAD);
    float s = 0.f;
#pragma unroll
    for (int j = 0; j < 4; j++) {
        float4 fv = f[j], av = a[j];
        s += fv.x * av.x + fv.y * av.y + fv.z * av.z + fv.w * av.w;
    }
    out[i] = s;
}

__global__ void gat_max_kernel(const int* __restrict__ src, const int* __restrict__ dst,
                               const float* __restrict__ el, const float* __restrict__ er,
                               unsigned* __restrict__ menc) {
    int e = blockIdx.x * blockDim.x + threadIdx.x;
    if (e >= NEDGE) return;
    int s = src[e], d = dst[e];
    float4 l = *(const float4*)(el + 4 * s);
    float4 r = *(const float4*)(er + 4 * d);
    atomicMax(menc + 4 * d + 0, encf(leaky(l.x + r.x)));
    atomicMax(menc + 4 * d + 1, encf(leaky(l.y + r.y)));
    atomicMax(menc + 4 * d + 2, encf(leaky(l.z + r.z)));
    atomicMax(menc + 4 * d + 3, encf(leaky(l.w + r.w)));
}

__global__ void gat_den_kernel(const int* __restrict__ src, const int* __restrict__ dst,
                               const float* __restrict__ el, const float* __restrict__ er,
                               const unsigned* __restrict__ menc, float* __restrict__ den) {
    int e = blockIdx.x * blockDim.x + threadIdx.x;
    if (e >= NEDGE) return;
    int s = src[e], d = dst[e];
    float4 l = *(const float4*)(el + 4 * s);
    float4 r = *(const float4*)(er + 4 * d);
    uint4 mu = *(const uint4*)(menc + 4 * d);
    atomicAdd(den + 4 * d + 0, __expf(leaky(l.x + r.x) - decf(mu.x)));
    atomicAdd(den + 4 * d + 1, __expf(leaky(l.y + r.y) - decf(mu.y)));
    atomicAdd(den + 4 * d + 2, __expf(leaky(l.z + r.z) - decf(mu.z)));
    atomicAdd(den + 4 * d + 3, __expf(leaky(l.w + r.w) - decf(mu.w)));
}

__global__ void gat_acc_kernel(const int* __restrict__ src, const int* __restrict__ dst,
                               const float* __restrict__ el, const float* __restrict__ er,
                               const unsigned* __restrict__ menc, const float* __restrict__ den,
                               const float* __restrict__ fs, float* __restrict__ out) {
    int t = blockIdx.x * blockDim.x + threadIdx.x;
    if (t >= NEDGE * NHEAD) return;
    int e = t >> 2, h = t & 3;
    int s = src[e], d = dst[e];
    float x = leaky(el[4 * s + h] + er[4 * d + h]);
    float m = decf(menc[4 * d + h]);
    float w = __expf(x - m) / fmaxf(den[4 * d + h], 1e-9f);
    const float* fr = fs + (long long)s * HID + h * DHEAD;
    float* orow = out + (long long)d * HID + h * DHEAD;
#pragma unroll
    for (int j = 0; j < DHEAD; j += 4) {
        float4 f = *(const float4*)(fr + j);
        atomicAdd(orow + j + 0, f.x * w);
        atomicAdd(orow + j + 1, f.y * w);
        atomicAdd(orow + j + 2, f.z * w);
        atomicAdd(orow + j + 3, f.w * w);
    }
}

__global__ void bias_relu_kernel(float* __restrict__ dst, const float* __restrict__ src,
                                 const float* __restrict__ ba, const float* __restrict__ bb) {
    long long i = (long long)blockIdx.x * blockDim.x + threadIdx.x;
    if (i >= NHF) return;
    int c = (int)(i & (HID - 1));
    float v = src[i] + ba[c];
    if (bb) v += bb[c];
    dst[i] = fmaxf(v, 0.f);
}

__global__ void compute_C_kernel(const float* ln1_gb, const float* attn_w, const float* attn_b,
                                 const float* ln2_gb, const float* ffn_w1, const float* ffn_b1,
                                 const float* ffn_w2, const float* ffn_b2, float* out) {
    float y1 = ln1_gb[1];
    float v = y1 * attn_w[2] + attn_b[2];
    float o = v * attn_w[3] + attn_b[3];
    float y2 = ln2_gb[1];
    float f = ffn_b2[0];
    for (int j = 0; j < 16; j++) {
        float z = y2 * ffn_w1[j] + ffn_b1[j];
        float g = 0.5f * z * (1.0f + erff(z * 0.70710678118654752f));
        f += g * ffn_w2[j];
    }
    out[0] = o + f;
}

__global__ void hf_kernel(const float* __restrict__ acc, const float* __restrict__ b1,
                          const float* __restrict__ Cs, float* __restrict__ hf) {
    int g = blockIdx.x * blockDim.x + threadIdx.x;
    int row = g >> 5;
    int lane = g & 31;
    if (row >= NPAP) return;
    float C = Cs[0];
    long long base = (long long)row * HID;
    float v0 = acc[base + lane]      + b1[lane]      + b1[64 + lane];
    float v1 = acc[base + lane + 32] + b1[lane + 32] + b1[96 + lane];
    float w0 = v0 + C, w1 = v1 + C;
    float s1 = v0 * v0 + v1 * v1;
    float s2 = w0 * w0 + w1 * w1;
#pragma unroll
    for (int o = 16; o; o >>= 1) {
        s1 += __shfl_xor_sync(0xFFFFFFFFu, s1, o);
        s2 += __shfl_xor_sync(0xFFFFFFFFu, s2, o);
    }
    float i1 = 1.f / fmaxf(sqrtf(s1), 1e-12f);
    float i2 = 1.f / fmaxf(sqrtf(s2), 1e-12f);
    long long hb = (long long)row * 128;
    hf[hb + lane]       = v0 * i1;
    hf[hb + lane + 32]  = v1 * i1;
    hf[hb + 64 + lane]  = w0 * i2;
    hf[hb + 96 + lane]  = w1 * i2;
}

extern "C" void kernel_launch(void* const* d_in, const int* in_sizes, int n_in,
                              void* d_out, int out_size) {
    const float* x_author = (const float*)d_in[0];
    const float* x_paper  = (const float*)d_in[1];
    const float* ntype    = (const float*)d_in[2];
    const float* W0       = (const float*)d_in[3];
    const float* al0      = (const float*)d_in[4];
    const float* ar0      = (const float*)d_in[5];
    const float* b0       = (const float*)d_in[6];
    const float* W1       = (const float*)d_in[7];
    const float* al1      = (const float*)d_in[8];
    const float* ar1      = (const float*)d_in[9];
    const float* b1       = (const float*)d_in[10];
    const float* ln1_gb   = (const float*)d_in[11];
    const float* attn_w   = (const float*)d_in[12];
    const float* attn_b   = (const float*)d_in[13];
    const float* ln2_gb   = (const float*)d_in[14];
    const float* ffn_w1   = (const float*)d_in[15];
    const float* ffn_b1   = (const float*)d_in[16];
    const float* ffn_w2   = (const float*)d_in[17];
    const float* ffn_b2   = (const float*)d_in[18];
    const float* lin_W    = (const float*)d_in[19];
    const float* lin_b    = (const float*)d_in[20];
    const int* src_w = (const int*)d_in[21];
    const int* dst_w = (const int*)d_in[22];
    const int* src_c = (const int*)d_in[23];
    const int* dst_c = (const int*)d_in[24];
    const int* src_r = (const int*)d_in[25];
    const int* dst_r = (const int*)d_in[26];
    float* out = (float*)d_out;

    float* S = nullptr;
    cudaGetSymbolAddress((void**)&S, g_scratch);

    float* ha   = S + OFF_HA;
    float* hp   = S + OFF_HP;
    float* Fa0  = S + OFF_FA0;
    float* Fp0  = S + OFF_FP0;
    float* Fp1  = S + OFF_FP1;
    float* Fp2  = S + OFF_FP2;
    float* Fa2  = S + OFF_FA2;
    float* outp = S + OFF_OUTP;
    float* outa = S + OFF_OUTA;
    float* ha1  = S + OFF_HA1;
    float* hp1  = S + OFF_HP1;
    float* F1a  = S + OFF_F1A;
    float* F1pd = S + OFF_F1PD;
    float* F1pc = S + OFF_F1PC;
    float* outp1 = S + OFF_OUTP1;
    float* hf   = S + OFF_HF;
    float* el_w  = S + OFF_EL + 0 * N4;
    float* er_w  = S + OFF_EL + 1 * N4;
    float* el_c  = S + OFF_EL + 2 * N4;
    float* er_c  = S + OFF_EL + 3 * N4;
    float* el_r  = S + OFF_EL + 4 * N4;
    float* er_r  = S + OFF_EL + 5 * N4;
    float* el1w  = S + OFF_EL + 6 * N4;
    float* er1w  = S + OFF_EL + 7 * N4;
    float* el1c  = S + OFF_EL + 8 * N4;
    float* er1c  = S + OFF_EL + 9 * N4;
    unsigned* m_w  = (unsigned*)(S + OFF_M + 0 * N4);
    unsigned* m_c  = (unsigned*)(S + OFF_M + 1 * N4);
    unsigned* m_r  = (unsigned*)(S + OFF_M + 2 * N4);
    unsigned* m1w  = (unsigned*)(S + OFF_M + 3 * N4);
    unsigned* m1c  = (unsigned*)(S + OFF_M + 4 * N4);
    float* den_w = S + OFF_DEN + 0 * N4;
    float* den_c = S + OFF_DEN + 1 * N4;
    float* den_r = S + OFF_DEN + 2 * N4;
    float* den1w = S + OFF_DEN + 3 * N4;
    float* den1c = S + OFF_DEN + 4 * N4;
    float* Cscalar = S + OFF_C;

    const int T = 256;
    auto blk = [](long long n) { return (unsigned)((n + 255) / 256); };

    fill_kernel<<<blk(5 * N4), T>>>((unsigned*)(S + OFF_M), ENC_NEG_INF, 5 * N4);
    fill_kernel<<<blk(5 * N4), T>>>((unsigned*)(S + OFF_DEN), 0u, 5 * N4);
    fill_kernel<<<blk(2 * NHF), T>>>((unsigned*)outp, 0u, 2 * NHF);
    fill_kernel<<<blk(NHF), T>>>((unsigned*)outp1, 0u, NHF);

    scale_kernel<<<blk(NI), T>>>(x_author, x_paper, ntype, ha, hp);

    dim3 g64(NAUT / 64, 1);
    gemm_kernel<<<g64, 256>>>(ha, W0 + 0 * 8192, nullptr, Fa0, IN_DIM, HID);
    gemm_kernel<<<g64, 256>>>(hp, W0 + 0 * 8192, nullptr, Fp0, IN_DIM, HID);
    gemm_kernel<<<g64, 256>>>(hp, W0 + 1 * 8192, nullptr, Fp1, IN_DIM, HID);
    gemm_kernel<<<g64, 256>>>(hp, W0 + 2 * 8192, nullptr, Fp2, IN_DIM, HID);
    gemm_kernel<<<g64, 256>>>(ha, W0 + 2 * 8192, nullptr, Fa2, IN_DIM, HID);

    eler_kernel<<<blk(N4), T>>>(Fa0, al0 + 0 * 64, el_w);
    eler_kernel<<<blk(N4), T>>>(Fp0, ar0 + 0 * 64, er_w);
    eler_kernel<<<blk(N4), T>>>(Fp1, al0 + 1 * 64, el_c);
    eler_kernel<<<blk(N4), T>>>(Fp1, ar0 + 1 * 64, er_c);
    eler_kernel<<<blk(N4), T>>>(Fp2, al0 + 2 * 64, el_r);
    eler_kernel<<<blk(N4), T>>>(Fa2, ar0 + 2 * 64, er_r);

    unsigned eb = blk(NEDGE), eb4 = blk((long long)NEDGE * NHEAD);
    gat_max_kernel<<<eb, T>>>(src_w, dst_w, el_w, er_w, m_w);
    gat_den_kernel<<<eb, T>>>(src_w, dst_w, el_w, er_w, m_w, den_w);
    gat_acc_kernel<<<eb4, T>>>(src_w, dst_w, el_w, er_w, m_w, den_w, Fa0, outp);

    gat_max_kernel<<<eb, T>>>(src_c, dst_c, el_c, er_c, m_c);
    gat_den_kernel<<<eb, T>>>(src_c, dst_c, el_c, er_c, m_c, den_c);
    gat_acc_kernel<<<eb4, T>>>(src_c, dst_c, el_c, er_c, m_c, den_c, Fp1, outp);

    gat_max_kernel<<<eb, T>>>(src_r, dst_r, el_r, er_r, m_r);
    gat_den_kernel<<<eb, T>>>(src_r, dst_r, el_r, er_r, m_r, den_r);
    gat_acc_kernel<<<eb4, T>>>(src_r, dst_r, el_r, er_r, m_r, den_r, Fp2, outa);

    bias_relu_kernel<<<blk(NHF), T>>>(hp1, outp, b0 + 0 * 64, b0 + 1 * 64);
    bias_relu_kernel<<<blk(NHF), T>>>(ha1, outa, b0 + 2 * 64, nullptr);

    gemm_kernel<<<g64, 256>>>(ha1, W1 + 0 * 4096, nullptr, F1a, HID, HID);
    gemm_kernel<<<g64, 256>>>(hp1, W1 + 0 * 4096, nullptr, F1pd, HID, HID);
    gemm_kernel<<<g64, 256>>>(hp1, W1 + 1 * 4096, nullptr, F1pc, HID, HID);

    eler_kernel<<<blk(N4), T>>>(F1a, al1 + 0 * 64, el1w);
    eler_kernel<<<blk(N4), T>>>(F1pd, ar1 + 0 * 64, er1w);
    eler_kernel<<<blk(N4), T>>>(F1pc, al1 + 1 * 64, el1c);
    eler_kernel<<<blk(N4), T>>>(F1pc, ar1 + 1 * 64, er1c);

    gat_max_kernel<<<eb, T>>>(src_w, dst_w, el1w, er1w, m1w);
    gat_den_kernel<<<eb, T>>>(src_w, dst_w, el1w, er1w, m1w, den1w);
    gat_acc_kernel<<<eb4, T>>>(src_w, dst_w, el1w, er1w, m1w, den1w, F1a, outp1);

    gat_max_kernel<<<eb, T>>>(src_c, dst_c, el1c, er1c, m1c);
    gat_den_kernel<<<eb, T>>>(src_c, dst_c, el1c, er1c, m1c, den1c);
    gat_acc_kernel<<<eb4, T>>>(src_c, dst_c, el1c, er1c, m1c, den1c, F1pc, outp1);

    compute_C_kernel<<<1, 1>>>(ln1_gb, attn_w, attn_b, ln2_gb,
                               ffn_w1, ffn_b1, ffn_w2, ffn_b2, Cscalar);
    hf_kernel<<<blk((long long)NPAP * 32), T>>>(outp1, b1, Cscalar, hf);

    dim3 gfin(NPAP / 64, (OUTF + 63) / 64);
    gemm_kernel<<<gfin, 256>>>(hf, lin_W, lin_b, out, 2 * HID, OUTF);
}

// round 2
// speedup vs baseline: 2.2563x; 2.2563x over previous
#include <cuda_runtime.h>

// ---------------------------------------------------------------------------
// HeteroGAT — CSR-gather formulation (no float atomics)
// ---------------------------------------------------------------------------

#define NAUT   16384
#define NPAP   16384
#define IN_DIM 128
#define HID    64
#define NHEAD  4
#define OUTF   349
#define NEDGE  262144
#define NNODE  16384          // both node sets have the same count
#define NEG_SLOPE 0.2f

constexpr long long NHF = (long long)NNODE * HID;       // 1,048,576
constexpr long long N4  = (long long)NNODE * NHEAD;     //    65,536

// ---- float scratch layout ----
constexpr long long OFF_FA0   = 0;
constexpr long long OFF_FP0   = OFF_FA0 + NHF;
constexpr long long OFF_FP1   = OFF_FP0 + NHF;
constexpr long long OFF_FP2   = OFF_FP1 + NHF;
constexpr long long OFF_FA2   = OFF_FP2 + NHF;
constexpr long long OFF_F1A   = OFF_FA2 + NHF;
constexpr long long OFF_F1PD  = OFF_F1A + NHF;
constexpr long long OFF_F1PC  = OFF_F1PD + NHF;
constexpr long long OFF_OUTP  = OFF_F1PC + NHF;
constexpr long long OFF_OUTA  = OFF_OUTP + NHF;   // unused slot kept for clarity
constexpr long long OFF_OUTP1 = OFF_OUTA + NHF;
constexpr long long OFF_HA1   = OFF_OUTP1 + NHF;
constexpr long long OFF_HP1   = OFF_HA1 + NHF;
constexpr long long OFF_HF    = OFF_HP1 + NHF;
constexpr long long OFF_ELER  = OFF_HF + 2 * NHF;       // 10 x N4
constexpr long long OFF_C     = OFF_ELER + 10 * N4;
// ---- int scratch (aliased on float array) ----
constexpr long long OFF_DEG   = OFF_C + 4;              // 3 * NNODE ints (also cursor)
constexpr long long OFF_RP    = OFF_DEG + 3LL * NNODE;  // 3 * (NNODE+1) ints
constexpr long long OFF_CSR   = OFF_RP + 3LL * (NNODE + 1); // 3 * NEDGE ints
constexpr long long SCRATCH_TOTAL = OFF_CSR + 3LL * NEDGE + 16;

__device__ float g_scratch[SCRATCH_TOTAL];

__device__ __forceinline__ float leaky(float x) {
    return x > 0.f ? x : NEG_SLOPE * x;
}

// ---------------------------------------------------------------------------
// CSR build
// ---------------------------------------------------------------------------
__global__ void zero_int_kernel(int* __restrict__ p, int n) {
    int i = blockIdx.x * blockDim.x + threadIdx.x;
    if (i < n) p[i] = 0;
}

__global__ void hist3_kernel(const int* __restrict__ d0, const int* __restrict__ d1,
                             const int* __restrict__ d2, int* __restrict__ deg) {
    int t = blockIdx.x * blockDim.x + threadIdx.x;
    if (t >= 3 * NEDGE) return;
    int g = t >> 18;               // /NEDGE
    int e = t & (NEDGE - 1);
    const int* ds = (g == 0) ? d0 : (g == 1) ? d1 : d2;
    atomicAdd(&deg[g * NNODE + ds[e]], 1);
}

// grid = 3 blocks of 1024; each block scans one graph's 16384 degrees.
// Writes row_ptr and re-writes deg[] as the scatter cursor.
__global__ __launch_bounds__(1024) void scan3_kernel(int* __restrict__ deg,
                                                     int* __restrict__ rp) {
    __shared__ int sh[1024];
    int t = threadIdx.x;
    int g = blockIdx.x;
    int* dg = deg + g * NNODE;
    int* r  = rp + g * (NNODE + 1);
    int loc[16];
    int run = 0;
    int base = t * 16;
#pragma unroll
    for (int i = 0; i < 16; i++) { loc[i] = run; run += dg[base + i]; }
    sh[t] = run;
    __syncthreads();
    for (int d = 1; d < 1024; d <<= 1) {
        int v = sh[t];
        int a = (t >= d) ? sh[t - d] : 0;
        __syncthreads();
        sh[t] = v + a;
        __syncthreads();
    }
    int off = (t == 0) ? 0 : sh[t - 1];
#pragma unroll
    for (int i = 0; i < 16; i++) {
        int v = off + loc[i];
        r[base + i] = v;
        dg[base + i] = v;     // cursor for scatter
    }
    if (t == 1023) r[NNODE] = off + run;
}

__global__ void scatter3_kernel(const int* __restrict__ s0, const int* __restrict__ d0,
                                const int* __restrict__ s1, const int* __restrict__ d1,
                                const int* __restrict__ s2, const int* __restrict__ d2,
                                int* __restrict__ cur, int* __restrict__ csr) {
    int t = blockIdx.x * blockDim.x + threadIdx.x;
    if (t >= 3 * NEDGE) return;
    int g = t >> 18;
    int e = t & (NEDGE - 1);
    const int* ss = (g == 0) ? s0 : (g == 1) ? s1 : s2;
    const int* ds = (g == 0) ? d0 : (g == 1) ? d1 : d2;
    int d = ds[e];
    int pos = atomicAdd(&cur[g * NNODE + d], 1);
    csr[(long long)g * NEDGE + pos] = ss[e];
}

// ---------------------------------------------------------------------------
// Batched GEMM: C[16384,64] = (A .* colscale) @ W[K,64]
// ---------------------------------------------------------------------------
struct Gemm5 {
    const float* A[5];
    const float* scale[5];
    const float* W[5];
    float* C[5];
    int K;
};

__global__ __launch_bounds__(256) void gemm64_kernel(Gemm5 p) {
    int b = blockIdx.y;
    const float* A  = p.A[b];
    const float* sc = p.scale[b];
    const float* W  = p.W[b];
    float* C        = p.C[b];
    int K = p.K;
    __shared__ __align__(16) float As[64][65];
    __shared__ __align__(16) float Ws[64][64];
    int row0 = blockIdx.x * 64;
    int tid = threadIdx.x;
    int tr = (tid >> 4) * 4;
    int tc = (tid & 15) * 4;
    float acc[4][4] = {};
    for (int kt = 0; kt < K; kt += 64) {
#pragma unroll
        for (int i = 0; i < 16; i++) {
            int idx = tid + i * 256;
            int r = idx >> 6, k = idx & 63;
            float v = A[(long long)(row0 + r) * K + kt + k];
            if (sc) v *= sc[kt + k];
            As[k][r] = v;
        }
#pragma unroll
        for (int i = 0; i < 16; i++) {
            int idx = tid + i * 256;
            int k = idx >> 6, c = idx & 63;
            Ws[k][c] = W[(long long)(kt + k) * 64 + c];
        }
        __syncthreads();
#pragma unroll 16
        for (int k = 0; k < 64; k++) {
            float a0 = As[k][tr], a1 = As[k][tr + 1], a2 = As[k][tr + 2], a3 = As[k][tr + 3];
            float4 w = *(const float4*)&Ws[k][tc];
            acc[0][0] += a0 * w.x; acc[0][1] += a0 * w.y; acc[0][2] += a0 * w.z; acc[0][3] += a0 * w.w;
            acc[1][0] += a1 * w.x; acc[1][1] += a1 * w.y; acc[1][2] += a1 * w.z; acc[1][3] += a1 * w.w;
            acc[2][0] += a2 * w.x; acc[2][1] += a2 * w.y; acc[2][2] += a2 * w.z; acc[2][3] += a2 * w.w;
            acc[3][0] += a3 * w.x; acc[3][1] += a3 * w.y; acc[3][2] += a3 * w.z; acc[3][3] += a3 * w.w;
        }
        __syncthreads();
    }
#pragma unroll
    for (int i = 0; i < 4; i++) {
        long long r = row0 + tr + i;
#pragma unroll
        for (int j = 0; j < 4; j++)
            C[r * 64 + tc + j] = acc[i][j];
    }
}

// ---- full GEMM (bias, arbitrary Ncols) for the final projection ----
__global__ __launch_bounds__(256) void gemm_full_kernel(
    const float* __restrict__ A, const float* __restrict__ W,
    const float* __restrict__ bias, float* __restrict__ C,
    int K, int Ncols) {
    __shared__ __align__(16) float As[64][65];
    __shared__ __align__(16) float Ws[64][64];
    int row0 = blockIdx.x * 64;
    int col0 = blockIdx.y * 64;
    int tid = threadIdx.x;
    int tr = (tid >> 4) * 4;
    int tc = (tid & 15) * 4;
    float acc[4][4] = {};
    for (int kt = 0; kt < K; kt += 64) {
#pragma unroll
        for (int i = 0; i < 16; i++) {
            int idx = tid + i * 256;
            int r = idx >> 6, k = idx & 63;
            As[k][r] = A[(long long)(row0 + r) * K + kt + k];
        }
#pragma unroll
        for (int i = 0; i < 16; i++) {
            int idx = tid + i * 256;
            int k = idx >> 6, c = idx & 63;
            int gc = col0 + c;
            Ws[k][c] = (gc < Ncols) ? W[(long long)(kt + k) * Ncols + gc] : 0.0f;
        }
        __syncthreads();
#pragma unroll 16
        for (int k = 0; k < 64; k++) {
            float a0 = As[k][tr], a1 = As[k][tr + 1], a2 = As[k][tr + 2], a3 = As[k][tr + 3];
            float4 w = *(const float4*)&Ws[k][tc];
            acc[0][0] += a0 * w.x; acc[0][1] += a0 * w.y; acc[0][2] += a0 * w.z; acc[0][3] += a0 * w.w;
            acc[1][0] += a1 * w.x; acc[1][1] += a1 * w.y; acc[1][2] += a1 * w.z; acc[1][3] += a1 * w.w;
            acc[2][0] += a2 * w.x; acc[2][1] += a2 * w.y; acc[2][2] += a2 * w.z; acc[2][3] += a2 * w.w;
            acc[3][0] += a3 * w.x; acc[3][1] += a3 * w.y; acc[3][2] += a3 * w.z; acc[3][3] += a3 * w.w;
        }
        __syncthreads();
    }
#pragma unroll
    for (int i = 0; i < 4; i++) {
        long long r = row0 + tr + i;
#pragma unroll
        for (int j = 0; j < 4; j++) {
            int c = col0 + tc + j;
            if (c < Ncols) C[r * Ncols + c] = acc[i][j] + bias[c];
        }
    }
}

// ---------------------------------------------------------------------------
// Batched attention-logit halves: out[n,h] = dot16(F[n,h,:], a[h,:])
// ---------------------------------------------------------------------------
struct Eler6 {
    const float* F[6];
    const float* a[6];
    float* out[6];
};

__global__ void eler_kernel(Eler6 p) {
    int b = blockIdx.y;
    const float* F = p.F[b];
    const float* avec = p.a[b];
    float* out = p.out[b];
    int i = blockIdx.x * blockDim.x + threadIdx.x;
    if (i >= NNODE * NHEAD) return;
    int node = i >> 2, h = i & 3;
    const float4* f = (const float4*)(F + (long long)node * HID + h * 16);
    const float4* a = (const float4*)(avec + h * 16);
    float s = 0.f;
#pragma unroll
    for (int j = 0; j < 4; j++) {
        float4 fv = f[j], av = a[j];
        s += fv.x * av.x + fv.y * av.y + fv.z * av.z + fv.w * av.w;
    }
    out[i] = s;
}

// ---------------------------------------------------------------------------
// Fused GAT: one warp per destination node. Online softmax in registers,
// shuffle merge, gather-accumulate. Optional prev-add / bias / relu epilogue.
// ---------------------------------------------------------------------------
#define MERGE(m, s)                                                        \
    {                                                                      \
        float om = __shfl_xor_sync(0xFFFFFFFFu, (m), off);                 \
        float os = __shfl_xor_sync(0xFFFFFFFFu, (s), off);                 \
        float nm = fmaxf((m), om);                                         \
        (s) = (s) * __expf((m) - nm) + os * __expf(om - nm);               \
        (m) = nm;                                                          \
    }

__global__ __launch_bounds__(256) void gat_kernel(
    const int* __restrict__ rp, const int* __restrict__ csr,
    const float* __restrict__ el, const float* __restrict__ er,
    const float* __restrict__ fs, const float* __restrict__ prev,
    const float* __restrict__ ba, const float* __restrict__ bb,
    int do_relu, float* __restrict__ out) {
    int w = (blockIdx.x * blockDim.x + threadIdx.x) >> 5;
    int lane = threadIdx.x & 31;
    if (w >= NNODE) return;
    int d = w;
    int beg = rp[d], end = rp[d + 1];
    float4 er4 = *(const float4*)(er + 4 * d);

    // ---- phase A: per-head online softmax stats ----
    float m0 = -1e30f, m1 = -1e30f, m2 = -1e30f, m3 = -1e30f;
    float s0 = 0.f, s1 = 0.f, s2 = 0.f, s3 = 0.f;
    for (int i = beg + lane; i < end; i += 32) {
        int s = csr[i];
        float4 l4 = *(const float4*)(el + 4 * s);
        float e0 = leaky(l4.x + er4.x);
        float e1 = leaky(l4.y + er4.y);
        float e2 = leaky(l4.z + er4.z);
        float e3 = leaky(l4.w + er4.w);
        float nm;
        nm = fmaxf(m0, e0); s0 = s0 * __expf(m0 - nm) + __expf(e0 - nm); m0 = nm;
        nm = fmaxf(m1, e1); s1 = s1 * __expf(m1 - nm) + __expf(e1 - nm); m1 = nm;
        nm = fmaxf(m2, e2); s2 = s2 * __expf(m2 - nm) + __expf(e2 - nm); m2 = nm;
        nm = fmaxf(m3, e3); s3 = s3 * __expf(m3 - nm) + __expf(e3 - nm); m3 = nm;
    }
#pragma unroll
    for (int off = 16; off; off >>= 1) {
        MERGE(m0, s0) MERGE(m1, s1) MERGE(m2, s2) MERGE(m3, s3)
    }
    float inv0 = 1.f / fmaxf(s0, 1e-9f);
    float inv1 = 1.f / fmaxf(s1, 1e-9f);
    float inv2 = 1.f / fmaxf(s2, 1e-9f);
    float inv3 = 1.f / fmaxf(s3, 1e-9f);

    // ---- phase B: weighted gather-accumulate ----
    // lane handles features f0=lane (head 0/1) and f1=lane+32 (head 2/3)
    bool hi = (lane & 16) != 0;
    float mA = hi ? m1 : m0, iA = hi ? inv1 : inv0, eA = hi ? er4.y : er4.x;
    float mB = hi ? m3 : m2, iB = hi ? inv3 : inv2, eB = hi ? er4.w : er4.z;
    float acc0 = 0.f, acc1 = 0.f;
    for (int i = beg; i < end; i++) {
        int s = csr[i];                               // broadcast
        float4 l4 = *(const float4*)(el + 4 * s);     // broadcast 16B
        float lA = hi ? l4.y : l4.x;
        float lB = hi ? l4.w : l4.z;
        float w0 = __expf(leaky(lA + eA) - mA) * iA;
        float w1 = __expf(leaky(lB + eB) - mB) * iB;
        const float* fr = fs + (long long)s * HID;
        acc0 += fr[lane] * w0;
        acc1 += fr[lane + 32] * w1;
    }
    long long ob = (long long)d * HID;
    if (prev) { acc0 += prev[ob + lane]; acc1 += prev[ob + lane + 32]; }
    if (ba)   { acc0 += ba[lane];        acc1 += ba[lane + 32]; }
    if (bb)   { acc0 += bb[lane];        acc1 += bb[lane + 32]; }
    if (do_relu) { acc0 = fmaxf(acc0, 0.f); acc1 = fmaxf(acc1, 0.f); }
    out[ob + lane] = acc0;
    out[ob + lane + 32] = acc1;
}

// ---------------------------------------------------------------------------
// Collapsed per-node transformer: _ln over a size-1 axis == its bias exactly,
// so the whole attention+FFN block reduces to one scalar C with h2 = h1 + C.
// ---------------------------------------------------------------------------
__global__ void compute_C_kernel(const float* ln1_gb, const float* attn_w, const float* attn_b,
                                 const float* ln2_gb, const float* ffn_w1, const float* ffn_b1,
                                 const float* ffn_w2, const float* ffn_b2, float* out) {
    float y1 = ln1_gb[1];
    float v = y1 * attn_w[2] + attn_b[2];
    float o = v * attn_w[3] + attn_b[3];
    float y2 = ln2_gb[1];
    float f = ffn_b2[0];
    for (int j = 0; j < 16; j++) {
        float z = y2 * ffn_w1[j] + ffn_b1[j];
        float g = 0.5f * z * (1.0f + erff(z * 0.70710678118654752f));
        f += g * ffn_w2[j];
    }
    out[0] = o + f;
}

// ---- hf: [l2norm(h1), l2norm(h1 + C)] per row; warp per row ----
__global__ void hf_kernel(const float* __restrict__ acc, const float* __restrict__ b1,
                          const float* __restrict__ Cs, float* __restrict__ hf) {
    int g = blockIdx.x * blockDim.x + threadIdx.x;
    int row = g >> 5;
    int lane = g & 31;
    if (row >= NPAP) return;
    float C = Cs[0];
    long long base = (long long)row * HID;
    float v0 = acc[base + lane]      + b1[lane]      + b1[64 + lane];
    float v1 = acc[base + lane + 32] + b1[lane + 32] + b1[96 + lane];
    float w0 = v0 + C, w1 = v1 + C;
    float s1 = v0 * v0 + v1 * v1;
    float s2 = w0 * w0 + w1 * w1;
#pragma unroll
    for (int o = 16; o; o >>= 1) {
        s1 += __shfl_xor_sync(0xFFFFFFFFu, s1, o);
        s2 += __shfl_xor_sync(0xFFFFFFFFu, s2, o);
    }
    float i1 = 1.f / fmaxf(sqrtf(s1), 1e-12f);
    float i2 = 1.f / fmaxf(sqrtf(s2), 1e-12f);
    long long hb = (long long)row * 128;
    hf[hb + lane]       = v0 * i1;
    hf[hb + lane + 32]  = v1 * i1;
    hf[hb + 64 + lane]  = w0 * i2;
    hf[hb + 96 + lane]  = w1 * i2;
}

// ---------------------------------------------------------------------------
extern "C" void kernel_launch(void* const* d_in, const int* in_sizes, int n_in,
                              void* d_out, int out_size) {
    const float* x_author = (const float*)d_in[0];
    const float* x_paper  = (const float*)d_in[1];
    const float* ntype    = (const float*)d_in[2];
    const float* W0       = (const float*)d_in[3];
    const float* al0      = (const float*)d_in[4];
    const float* ar0      = (const float*)d_in[5];
    const float* b0       = (const float*)d_in[6];
    const float* W1       = (const float*)d_in[7];
    const float* al1      = (const float*)d_in[8];
    const float* ar1      = (const float*)d_in[9];
    const float* b1       = (const float*)d_in[10];
    const float* ln1_gb   = (const float*)d_in[11];
    const float* attn_w   = (const float*)d_in[12];
    const float* attn_b   = (const float*)d_in[13];
    const float* ln2_gb   = (const float*)d_in[14];
    const float* ffn_w1   = (const float*)d_in[15];
    const float* ffn_b1   = (const float*)d_in[16];
    const float* ffn_w2   = (const float*)d_in[17];
    const float* ffn_b2   = (const float*)d_in[18];
    const float* lin_W    = (const float*)d_in[19];
    const float* lin_b    = (const float*)d_in[20];
    const int* src_w = (const int*)d_in[21];
    const int* dst_w = (const int*)d_in[22];
    const int* src_c = (const int*)d_in[23];
    const int* dst_c = (const int*)d_in[24];
    const int* src_r = (const int*)d_in[25];
    const int* dst_r = (const int*)d_in[26];
    float* out = (float*)d_out;

    float* S = nullptr;
    cudaGetSymbolAddress((void**)&S, g_scratch);

    float* Fa0  = S + OFF_FA0;
    float* Fp0  = S + OFF_FP0;
    float* Fp1  = S + OFF_FP1;
    float* Fp2  = S + OFF_FP2;
    float* Fa2  = S + OFF_FA2;
    float* F1a  = S + OFF_F1A;
    float* F1pd = S + OFF_F1PD;
    float* F1pc = S + OFF_F1PC;
    float* outp  = S + OFF_OUTP;
    float* outp1 = S + OFF_OUTP1;
    float* ha1  = S + OFF_HA1;
    float* hp1  = S + OFF_HP1;
    float* hf   = S + OFF_HF;
    float* el_w = S + OFF_ELER + 0 * N4;
    float* er_w = S + OFF_ELER + 1 * N4;
    float* el_c = S + OFF_ELER + 2 * N4;
    float* er_c = S + OFF_ELER + 3 * N4;
    float* el_r = S + OFF_ELER + 4 * N4;
    float* er_r = S + OFF_ELER + 5 * N4;
    float* el1w = S + OFF_ELER + 6 * N4;
    float* er1w = S + OFF_ELER + 7 * N4;
    float* el1c = S + OFF_ELER + 8 * N4;
    float* er1c = S + OFF_ELER + 9 * N4;
    float* Cscalar = S + OFF_C;
    int* degB = (int*)(S + OFF_DEG);
    int* rpB  = (int*)(S + OFF_RP);
    int* csrB = (int*)(S + OFF_CSR);

    const int T = 256;

    // ---- CSR build (3 graphs: 0=writes, 1=cites, 2=revw) ----
    zero_int_kernel<<<(3 * NNODE + T - 1) / T, T>>>(degB, 3 * NNODE);
    hist3_kernel<<<(3 * NEDGE + T - 1) / T, T>>>(dst_w, dst_c, dst_r, degB);
    scan3_kernel<<<3, 1024>>>(degB, rpB);
    scatter3_kernel<<<(3 * NEDGE + T - 1) / T, T>>>(src_w, dst_w, src_c, dst_c,
                                                    src_r, dst_r, degB, csrB);
    const int* rp_w = rpB + 0 * (NNODE + 1);
    const int* rp_c = rpB + 1 * (NNODE + 1);
    const int* rp_r = rpB + 2 * (NNODE + 1);
    const int* csr_w = csrB + 0LL * NEDGE;
    const int* csr_c = csrB + 1LL * NEDGE;
    const int* csr_r = csrB + 2LL * NEDGE;

    // ---- layer 0: 5 GEMMs batched (scale fused into A-load) ----
    Gemm5 g0;
    g0.A[0] = x_author; g0.scale[0] = ntype;            g0.W[0] = W0 + 0 * 8192; g0.C[0] = Fa0;
    g0.A[1] = x_paper;  g0.scale[1] = ntype + IN_DIM;   g0.W[1] = W0 + 0 * 8192; g0.C[1] = Fp0;
    g0.A[2] = x_paper;  g0.scale[2] = ntype + IN_DIM;   g0.W[2] = W0 + 1 * 8192; g0.C[2] = Fp1;
    g0.A[3] = x_paper;  g0.scale[3] = ntype + IN_DIM;   g0.W[3] = W0 + 2 * 8192; g0.C[3] = Fp2;
    g0.A[4] = x_author; g0.scale[4] = ntype;            g0.W[4] = W0 + 2 * 8192; g0.C[4] = Fa2;
    g0.K = IN_DIM;
    gemm64_kernel<<<dim3(NNODE / 64, 5), 256>>>(g0);

    Eler6 e0;
    e0.F[0] = Fa0; e0.a[0] = al0 + 0 * 64; e0.out[0] = el_w;
    e0.F[1] = Fp0; e0.a[1] = ar0 + 0 * 64; e0.out[1] = er_w;
    e0.F[2] = Fp1; e0.a[2] = al0 + 1 * 64; e0.out[2] = el_c;
    e0.F[3] = Fp1; e0.a[3] = ar0 + 1 * 64; e0.out[3] = er_c;
    e0.F[4] = Fp2; e0.a[4] = al0 + 2 * 64; e0.out[4] = el_r;
    e0.F[5] = Fa2; e0.a[5] = ar0 + 2 * 64; e0.out[5] = er_r;
    eler_kernel<<<dim3((int)(N4 / T), 6), T>>>(e0);

    unsigned gb = (NNODE * 32) / T;   // one warp per dst node
    // writes: authors -> papers (raw into outp)
    gat_kernel<<<gb, T>>>(rp_w, csr_w, el_w, er_w, Fa0, nullptr, nullptr, nullptr, 0, outp);
    // revw: papers -> authors, ha1 = relu(acc + b0[2])
    gat_kernel<<<gb, T>>>(rp_r, csr_r, el_r, er_r, Fp2, nullptr, b0 + 128, nullptr, 1, ha1);
    // cites: papers -> papers, hp1 = relu(outp + acc + b0[0] + b0[1])
    gat_kernel<<<gb, T>>>(rp_c, csr_c, el_c, er_c, Fp1, outp, b0, b0 + 64, 1, hp1);

    // ---- layer 1: 3 GEMMs batched (revw GAT is dead code downstream) ----
    Gemm5 g1;
    g1.A[0] = ha1; g1.scale[0] = nullptr; g1.W[0] = W1 + 0 * 4096; g1.C[0] = F1a;
    g1.A[1] = hp1; g1.scale[1] = nullptr; g1.W[1] = W1 + 0 * 4096; g1.C[1] = F1pd;
    g1.A[2] = hp1; g1.scale[2] = nullptr; g1.W[2] = W1 + 1 * 4096; g1.C[2] = F1pc;
    g1.A[3] = g1.A[4] = nullptr; g1.scale[3] = g1.scale[4] = nullptr;
    g1.W[3] = g1.W[4] = nullptr; g1.C[3] = g1.C[4] = nullptr;
    g1.K = HID;
    gemm64_kernel<<<dim3(NNODE / 64, 3), 256>>>(g1);

    Eler6 e1;
    e1.F[0] = F1a;  e1.a[0] = al1 + 0 * 64; e1.out[0] = el1w;
    e1.F[1] = F1pd; e1.a[1] = ar1 + 0 * 64; e1.out[1] = er1w;
    e1.F[2] = F1pc; e1.a[2] = al1 + 1 * 64; e1.out[2] = el1c;
    e1.F[3] = F1pc; e1.a[3] = ar1 + 1 * 64; e1.out[3] = er1c;
    e1.F[4] = e1.F[5] = nullptr; e1.a[4] = e1.a[5] = nullptr; e1.out[4] = e1.out[5] = nullptr;
    eler_kernel<<<dim3((int)(N4 / T), 4), T>>>(e1);

    gat_kernel<<<gb, T>>>(rp_w, csr_w, el1w, er1w, F1a, nullptr, nullptr, nullptr, 0, outp1);
    gat_kernel<<<gb, T>>>(rp_c, csr_c, el1c, er1c, F1pc, outp1, nullptr, nullptr, 0, outp1);

    // ---- collapsed transformer scalar + normalized concat ----
    compute_C_kernel<<<1, 1>>>(ln1_gb, attn_w, attn_b, ln2_gb,
                               ffn_w1, ffn_b1, ffn_w2, ffn_b2, Cscalar);
    hf_kernel<<<(NPAP * 32) / T, T>>>(outp1, b1, Cscalar, hf);

    // ---- final projection: [16384,128] @ [128,349] + bias ----
    gemm_full_kernel<<<dim3(NPAP / 64, (OUTF + 63) / 64), 256>>>(hf, lin_W, lin_b, out,
                                                                 2 * HID, OUTF);
}